// round 4
// baseline (speedup 1.0000x reference)
#include <cuda_runtime.h>

// PersistenceLandscapeEncoder: pairs (32768,2) f32 -> landscapes (5,4096) f32.
//
// tent_i(t) = min(t-b_i, d_i-t) clamped at 0.  With m=(b+d)/2:
//   m <  t  ->  value = d - t   (take top-5 deaths on the left)
//   m >= t  ->  value = t - b   (take bot-5 births on the right)
// Buckets are ALIGNED to the t-grid (4096 buckets, edges at t_j), so column j's
// answer = top5( {prefixTop5d(buckets<j) - t}+  U  {t - suffixBot5b(buckets>=j)}+ ).
// Prefix/suffix 5-lists come from a binary-lifting tree (levels 0..6) plus a
// 64-wide coarse exclusive scan -- no long serial scans, no home-bucket loop.

#define N_PAIRS 32768
#define RES     4096
#define NB      4096
#define CAP     64
#define NEGINF  (-3.0e38f)
#define POSINF  (3.0e38f)

// level bases: L0=4096 nodes, L1=2048, ..., L6=64.  node(l,i) at BASE[l]+i.
#define B0 0
#define B1 4096
#define B2 6144
#define B3 7168
#define B4 7680
#define B5 7936
#define B6 8064
#define NODES 8128

__device__ float  g_tmin, g_dt, g_scale;
__device__ int    g_count[NB];
__device__ float2 g_slab[NB * CAP];
__device__ float  g_Td[NODES * 5];   // tree of top-5 deaths (desc)
__device__ float  g_Tb[NODES * 5];   // tree of bot-5 births (asc)
__device__ float  g_Pc[64 * 5];      // coarse exclusive prefix (desc d)
__device__ float  g_Sc[64 * 5];      // coarse exclusive suffix (asc b)

// ---- sorted 5-list networks (static indices only) --------------------------
__device__ __forceinline__ void merge_desc(
    float& a0, float& a1, float& a2, float& a3, float& a4,
    float b0, float b1, float b2, float b3, float b4)
{
    float m0 = fmaxf(a0, b0);
    float m1 = fmaxf(fmaxf(a1, b1), fminf(a0, b0));
    float m2 = fmaxf(fmaxf(a2, b2), fmaxf(fminf(a0, b1), fminf(a1, b0)));
    float m3 = fmaxf(fmaxf(a3, b3),
               fmaxf(fminf(a0, b2), fmaxf(fminf(a1, b1), fminf(a2, b0))));
    float m4 = fmaxf(fmaxf(a4, b4),
               fmaxf(fmaxf(fminf(a0, b3), fminf(a1, b2)),
                     fmaxf(fminf(a2, b1), fminf(a3, b0))));
    a0 = m0; a1 = m1; a2 = m2; a3 = m3; a4 = m4;
}

__device__ __forceinline__ void merge_asc(
    float& a0, float& a1, float& a2, float& a3, float& a4,
    float b0, float b1, float b2, float b3, float b4)
{
    float m0 = fminf(a0, b0);
    float m1 = fminf(fminf(a1, b1), fmaxf(a0, b0));
    float m2 = fminf(fminf(a2, b2), fminf(fmaxf(a0, b1), fmaxf(a1, b0)));
    float m3 = fminf(fminf(a3, b3),
               fminf(fmaxf(a0, b2), fminf(fmaxf(a1, b1), fmaxf(a2, b0))));
    float m4 = fminf(fminf(a4, b4),
               fminf(fminf(fmaxf(a0, b3), fmaxf(a1, b2)),
                     fminf(fmaxf(a2, b1), fmaxf(a3, b0))));
    a0 = m0; a1 = m1; a2 = m2; a3 = m3; a4 = m4;
}

__device__ __forceinline__ void insert_desc(
    float& t0, float& t1, float& t2, float& t3, float& t4, float v)
{
    if (v > t4) {
        t4 = v;
        if (t4 > t3) { float x = t4; t4 = t3; t3 = x;
          if (t3 > t2) { x = t3; t3 = t2; t2 = x;
            if (t2 > t1) { x = t2; t2 = t1; t1 = x;
              if (t1 > t0) { x = t1; t1 = t0; t0 = x; }
            }
          }
        }
    }
}

__device__ __forceinline__ void insert_asc(
    float& t0, float& t1, float& t2, float& t3, float& t4, float v)
{
    if (v < t4) {
        t4 = v;
        if (t4 < t3) { float x = t4; t4 = t3; t3 = x;
          if (t3 < t2) { x = t3; t3 = t2; t2 = x;
            if (t2 < t1) { x = t2; t2 = t1; t1 = x;
              if (t1 < t0) { x = t1; t1 = t0; t0 = x; }
            }
          }
        }
    }
}

__device__ __forceinline__ void load5(const float* p, float& a0, float& a1,
                                      float& a2, float& a3, float& a4)
{ a0 = p[0]; a1 = p[1]; a2 = p[2]; a3 = p[3]; a4 = p[4]; }

__device__ __forceinline__ void store5(float* p, float a0, float a1,
                                       float a2, float a3, float a4)
{ p[0] = a0; p[1] = a1; p[2] = a2; p[3] = a3; p[4] = a4; }

// ---------------------------------------------------------------------------
// K1: minmax (shfl) + reset counters.
// ---------------------------------------------------------------------------
__global__ void __launch_bounds__(1024) minmax_kernel(const float2* __restrict__ pairs) {
    __shared__ float smn[32], smx[32];
    const int tid = threadIdx.x;
    #pragma unroll
    for (int i = 0; i < NB / 1024; i++) g_count[tid + i * 1024] = 0;

    const float4* p4 = (const float4*)pairs;          // (b0,d0,b1,d1)
    float mn = POSINF, mx = NEGINF;
    #pragma unroll
    for (int i = 0; i < (N_PAIRS / 2) / 1024; i++) {
        float4 v = p4[tid + i * 1024];
        mn = fminf(mn, fminf(v.x, v.z));
        mx = fmaxf(mx, fmaxf(v.y, v.w));
    }
    #pragma unroll
    for (int off = 16; off >= 1; off >>= 1) {
        mn = fminf(mn, __shfl_xor_sync(0xffffffffu, mn, off));
        mx = fmaxf(mx, __shfl_xor_sync(0xffffffffu, mx, off));
    }
    if ((tid & 31) == 0) { smn[tid >> 5] = mn; smx[tid >> 5] = mx; }
    __syncthreads();
    if (tid < 32) {
        mn = smn[tid]; mx = smx[tid];
        #pragma unroll
        for (int off = 16; off >= 1; off >>= 1) {
            mn = fminf(mn, __shfl_xor_sync(0xffffffffu, mn, off));
            mx = fmaxf(mx, __shfl_xor_sync(0xffffffffu, mx, off));
        }
        if (tid == 0) {
            float span = fmaxf(mx - mn, 1e-30f);
            g_tmin  = mn;
            g_dt    = span / (float)(RES - 1);
            g_scale = (float)(RES - 1) / span;
        }
    }
}

// ---------------------------------------------------------------------------
// K2: scatter pairs into grid-aligned midpoint buckets.
// ---------------------------------------------------------------------------
__global__ void __launch_bounds__(256) scatter_kernel(const float2* __restrict__ pairs) {
    const float tmin = g_tmin, scale = g_scale;
    const int i = blockIdx.x * 256 + threadIdx.x;
    float2 p = pairs[i];
    float m = 0.5f * (p.x + p.y);
    int b = (int)((m - tmin) * scale);
    b = min(NB - 1, max(0, b));
    int pos = atomicAdd(&g_count[b], 1);
    if (pos < CAP) g_slab[b * CAP + pos] = p;
}

// ---------------------------------------------------------------------------
// K3: level-0 nodes: per-bucket top-5 death (desc) / bot-5 birth (asc).
// ---------------------------------------------------------------------------
__global__ void __launch_bounds__(256) level0_kernel() {
    const int i = blockIdx.x * 256 + threadIdx.x;   // bucket id, 0..4095
    const int n = min(g_count[i], CAP);
    float d0=NEGINF,d1=NEGINF,d2=NEGINF,d3=NEGINF,d4=NEGINF;
    float b0=POSINF,b1=POSINF,b2=POSINF,b3=POSINF,b4=POSINF;
    const float2* s = &g_slab[i * CAP];
    for (int k = 0; k < n; k++) {
        float2 p = s[k];
        insert_desc(d0, d1, d2, d3, d4, p.y);
        insert_asc (b0, b1, b2, b3, b4, p.x);
    }
    store5(&g_Td[(B0 + i) * 5], d0, d1, d2, d3, d4);
    store5(&g_Tb[(B0 + i) * 5], b0, b1, b2, b3, b4);
}

// ---------------------------------------------------------------------------
// K4: build tree levels 1..6 + 64-wide coarse exclusive prefix/suffix scans.
// ---------------------------------------------------------------------------
__global__ void __launch_bounds__(1024) build_kernel() {
    __shared__ float sP[2][64][5], sS[2][64][5];
    const int tid = threadIdx.x;
    const int bases[7] = {B0, B1, B2, B3, B4, B5, B6};

    #pragma unroll
    for (int l = 1; l <= 6; l++) {
        const int n = NB >> l;
        for (int i = tid; i < n; i += 1024) {
            const float* c0 = &g_Td[(bases[l-1] + 2*i    ) * 5];
            const float* c1 = &g_Td[(bases[l-1] + 2*i + 1) * 5];
            float a0,a1,a2,a3,a4; load5(c0, a0,a1,a2,a3,a4);
            merge_desc(a0,a1,a2,a3,a4, c1[0],c1[1],c1[2],c1[3],c1[4]);
            store5(&g_Td[(bases[l] + i) * 5], a0,a1,a2,a3,a4);

            const float* e0 = &g_Tb[(bases[l-1] + 2*i    ) * 5];
            const float* e1 = &g_Tb[(bases[l-1] + 2*i + 1) * 5];
            float u0,u1,u2,u3,u4; load5(e0, u0,u1,u2,u3,u4);
            merge_asc(u0,u1,u2,u3,u4, e1[0],e1[1],e1[2],e1[3],e1[4]);
            store5(&g_Tb[(bases[l] + i) * 5], u0,u1,u2,u3,u4);
        }
        __syncthreads();
    }

    // coarse exclusive scans over the 64 level-6 superbuckets.
    if (tid < 64) {                 // prefix of d-tops (shifted: exclusive)
        if (tid > 0) load5(&g_Td[(B6 + tid - 1) * 5],
                           sP[0][tid][0], sP[0][tid][1], sP[0][tid][2],
                           sP[0][tid][3], sP[0][tid][4]);
        else { sP[0][0][0]=NEGINF; sP[0][0][1]=NEGINF; sP[0][0][2]=NEGINF;
               sP[0][0][3]=NEGINF; sP[0][0][4]=NEGINF; }
    } else if (tid < 128) {         // suffix of b-bots (shifted: exclusive)
        int s = tid - 64;
        if (s < 63) load5(&g_Tb[(B6 + s + 1) * 5],
                          sS[0][s][0], sS[0][s][1], sS[0][s][2],
                          sS[0][s][3], sS[0][s][4]);
        else { sS[0][63][0]=POSINF; sS[0][63][1]=POSINF; sS[0][63][2]=POSINF;
               sS[0][63][3]=POSINF; sS[0][63][4]=POSINF; }
    }
    __syncthreads();

    int cur = 0;
    #pragma unroll
    for (int off = 1; off < 64; off <<= 1) {
        if (tid < 64) {
            float a0,a1,a2,a3,a4;
            load5(sP[cur][tid], a0,a1,a2,a3,a4);
            if (tid >= off)
                merge_desc(a0,a1,a2,a3,a4,
                           sP[cur][tid-off][0], sP[cur][tid-off][1],
                           sP[cur][tid-off][2], sP[cur][tid-off][3],
                           sP[cur][tid-off][4]);
            store5(sP[cur^1][tid], a0,a1,a2,a3,a4);
        } else if (tid < 128) {
            int s = tid - 64;
            float a0,a1,a2,a3,a4;
            load5(sS[cur][s], a0,a1,a2,a3,a4);
            if (s + off < 64)
                merge_asc(a0,a1,a2,a3,a4,
                          sS[cur][s+off][0], sS[cur][s+off][1],
                          sS[cur][s+off][2], sS[cur][s+off][3],
                          sS[cur][s+off][4]);
            store5(sS[cur^1][s], a0,a1,a2,a3,a4);
        }
        cur ^= 1;
        __syncthreads();
    }
    if (tid < 64)
        store5(&g_Pc[tid * 5], sP[cur][tid][0], sP[cur][tid][1],
               sP[cur][tid][2], sP[cur][tid][3], sP[cur][tid][4]);
    else if (tid < 128) {
        int s = tid - 64;
        store5(&g_Sc[s * 5], sS[cur][s][0], sS[cur][s][1],
               sS[cur][s][2], sS[cur][s][3], sS[cur][s][4]);
    }
}

// ---------------------------------------------------------------------------
// K5: per-column binary-lifting assembly + output.
// ---------------------------------------------------------------------------
__global__ void __launch_bounds__(128) landscape_kernel(float* __restrict__ out)
{
    const int j = blockIdx.x * 128 + threadIdx.x;     // column 0..4095
    const float t = g_tmin + (float)j * g_dt;
    const int sb = j >> 6;
    const int lo = j & 63;
    const int bases[7] = {B0, B1, B2, B3, B4, B5, B6};

    // ---- prefix (buckets [0, j)): coarse + fine high-to-low bits of lo ----
    float p0,p1,p2,p3,p4;
    load5(&g_Pc[sb * 5], p0,p1,p2,p3,p4);
    {
        int lpos = 0;
        #pragma unroll
        for (int l = 5; l >= 0; l--) {
            if ((lo >> l) & 1) {
                int idx = (sb << (6 - l)) + (lpos >> l);
                const float* nd = &g_Td[(bases[l] + idx) * 5];
                merge_desc(p0,p1,p2,p3,p4, nd[0],nd[1],nd[2],nd[3],nd[4]);
                lpos += 1 << l;
            }
        }
    }

    // ---- suffix (buckets [j, 4096)): coarse + fine low-to-high bits ----
    float s0,s1,s2,s3,s4;
    load5(&g_Sc[sb * 5], s0,s1,s2,s3,s4);
    if (lo == 0) {
        const float* nd = &g_Tb[(B6 + sb) * 5];
        merge_asc(s0,s1,s2,s3,s4, nd[0],nd[1],nd[2],nd[3],nd[4]);
    } else {
        int lpos = lo;
        #pragma unroll
        for (int l = 0; l <= 5; l++) {
            if ((lpos >> l) & 1) {
                int idx = (sb << (6 - l)) + (lpos >> l);
                const float* nd = &g_Tb[(bases[l] + idx) * 5];
                merge_asc(s0,s1,s2,s3,s4, nd[0],nd[1],nd[2],nd[3],nd[4]);
                lpos += 1 << l;
            }
        }
    }

    // transform to tent values, clamp at 0 (preserves sort order), merge.
    p0 = fmaxf(p0 - t, 0.0f); p1 = fmaxf(p1 - t, 0.0f); p2 = fmaxf(p2 - t, 0.0f);
    p3 = fmaxf(p3 - t, 0.0f); p4 = fmaxf(p4 - t, 0.0f);
    float q0 = fmaxf(t - s0, 0.0f), q1 = fmaxf(t - s1, 0.0f);
    float q2 = fmaxf(t - s2, 0.0f), q3 = fmaxf(t - s3, 0.0f);
    float q4 = fmaxf(t - s4, 0.0f);
    merge_desc(p0,p1,p2,p3,p4, q0,q1,q2,q3,q4);

    out[0 * RES + j] = p0;
    out[1 * RES + j] = p1;
    out[2 * RES + j] = p2;
    out[3 * RES + j] = p3;
    out[4 * RES + j] = p4;
}

extern "C" void kernel_launch(void* const* d_in, const int* in_sizes, int n_in,
                              void* d_out, int out_size) {
    const float2* pairs = (const float2*)d_in[0];
    float* out = (float*)d_out;

    minmax_kernel   <<<1, 1024>>>(pairs);
    scatter_kernel  <<<N_PAIRS / 256, 256>>>(pairs);
    level0_kernel   <<<NB / 256, 256>>>();
    build_kernel    <<<1, 1024>>>();
    landscape_kernel<<<RES / 128, 128>>>(out);
}

// round 6
// speedup vs baseline: 1.8837x; 1.8837x over previous
#include <cuda_runtime.h>

// PersistenceLandscapeEncoder: pairs (32768,2) f32 -> landscapes (5,4096) f32.
//
// tent_i(t) = min(t-b_i, d_i-t) clamped at 0.  With m=(b+d)/2:
//   m <  t  ->  value = d - t   (top-5 deaths among buckets left of column)
//   m >= t  ->  value = t - b   (bot-5 births among buckets right/at column)
// Buckets aligned to the t-grid (4096, edges at t_j).  Column j:
//   top5 = merge( {prefixTop5d(buckets<j) - t}+ , {t - suffixBot5b(buckets>=j)}+ )
//
// Structure (all latency-flat):
//   K1  minmax + counter reset                  (1 block, 2 barriers)
//   K2  scatter into buckets                    (128 blocks)
//   K3  warp per 32-bucket group: level-0 lists + shfl prefix/suffix scans
//   K4  block per 128 columns: redundant 128-group coarse scan in smem,
//       then 2 merges per column.

#define N_PAIRS 32768
#define RES     4096
#define NB      4096
#define CAP     64
#define NGROUP  128          // NB / 32
#define NEGINF  (-3.0e38f)
#define POSINF  (3.0e38f)

__device__ float  g_tmin, g_dt, g_scale;
__device__ int    g_count[NB];
__device__ float2 g_slab[NB * CAP];
__device__ float  g_Pf[NB][5];      // within-group EXCLUSIVE prefix top-5 d (desc)
__device__ float  g_Sf[NB][5];      // within-group INCLUSIVE suffix bot-5 b (asc)
__device__ float  g_GT[NGROUP][5];  // group total top-5 d (desc)
__device__ float  g_GB[NGROUP][5];  // group total bot-5 b (asc)

// ---- sorted 5-list networks (static indices only) --------------------------
__device__ __forceinline__ void merge_desc(
    float& a0, float& a1, float& a2, float& a3, float& a4,
    float b0, float b1, float b2, float b3, float b4)
{
    float m0 = fmaxf(a0, b0);
    float m1 = fmaxf(fmaxf(a1, b1), fminf(a0, b0));
    float m2 = fmaxf(fmaxf(a2, b2), fmaxf(fminf(a0, b1), fminf(a1, b0)));
    float m3 = fmaxf(fmaxf(a3, b3),
               fmaxf(fminf(a0, b2), fmaxf(fminf(a1, b1), fminf(a2, b0))));
    float m4 = fmaxf(fmaxf(a4, b4),
               fmaxf(fmaxf(fminf(a0, b3), fminf(a1, b2)),
                     fmaxf(fminf(a2, b1), fminf(a3, b0))));
    a0 = m0; a1 = m1; a2 = m2; a3 = m3; a4 = m4;
}

__device__ __forceinline__ void merge_asc(
    float& a0, float& a1, float& a2, float& a3, float& a4,
    float b0, float b1, float b2, float b3, float b4)
{
    float m0 = fminf(a0, b0);
    float m1 = fminf(fminf(a1, b1), fmaxf(a0, b0));
    float m2 = fminf(fminf(a2, b2), fminf(fmaxf(a0, b1), fmaxf(a1, b0)));
    float m3 = fminf(fminf(a3, b3),
               fminf(fmaxf(a0, b2), fminf(fmaxf(a1, b1), fmaxf(a2, b0))));
    float m4 = fminf(fminf(a4, b4),
               fminf(fminf(fmaxf(a0, b3), fmaxf(a1, b2)),
                     fminf(fmaxf(a2, b1), fmaxf(a3, b0))));
    a0 = m0; a1 = m1; a2 = m2; a3 = m3; a4 = m4;
}

__device__ __forceinline__ void insert_desc(
    float& t0, float& t1, float& t2, float& t3, float& t4, float v)
{
    if (v > t4) {
        t4 = v;
        if (t4 > t3) { float x = t4; t4 = t3; t3 = x;
          if (t3 > t2) { x = t3; t3 = t2; t2 = x;
            if (t2 > t1) { x = t2; t2 = t1; t1 = x;
              if (t1 > t0) { x = t1; t1 = t0; t0 = x; }
            }
          }
        }
    }
}

__device__ __forceinline__ void insert_asc(
    float& t0, float& t1, float& t2, float& t3, float& t4, float v)
{
    if (v < t4) {
        t4 = v;
        if (t4 < t3) { float x = t4; t4 = t3; t3 = x;
          if (t3 < t2) { x = t3; t3 = t2; t2 = x;
            if (t2 < t1) { x = t2; t2 = t1; t1 = x;
              if (t1 < t0) { x = t1; t1 = t0; t0 = x; }
            }
          }
        }
    }
}

// ---------------------------------------------------------------------------
// K1: minmax (shfl) + reset counters.
// ---------------------------------------------------------------------------
__global__ void __launch_bounds__(1024) minmax_kernel(const float2* __restrict__ pairs) {
    __shared__ float smn[32], smx[32];
    const int tid = threadIdx.x;
    #pragma unroll
    for (int i = 0; i < NB / 1024; i++) g_count[tid + i * 1024] = 0;

    const float4* p4 = (const float4*)pairs;          // (b0,d0,b1,d1)
    float mn = POSINF, mx = NEGINF;
    #pragma unroll
    for (int i = 0; i < (N_PAIRS / 2) / 1024; i++) {
        float4 v = p4[tid + i * 1024];
        mn = fminf(mn, fminf(v.x, v.z));
        mx = fmaxf(mx, fmaxf(v.y, v.w));
    }
    #pragma unroll
    for (int off = 16; off >= 1; off >>= 1) {
        mn = fminf(mn, __shfl_xor_sync(0xffffffffu, mn, off));
        mx = fmaxf(mx, __shfl_xor_sync(0xffffffffu, mx, off));
    }
    if ((tid & 31) == 0) { smn[tid >> 5] = mn; smx[tid >> 5] = mx; }
    __syncthreads();
    if (tid < 32) {
        mn = smn[tid]; mx = smx[tid];
        #pragma unroll
        for (int off = 16; off >= 1; off >>= 1) {
            mn = fminf(mn, __shfl_xor_sync(0xffffffffu, mn, off));
            mx = fmaxf(mx, __shfl_xor_sync(0xffffffffu, mx, off));
        }
        if (tid == 0) {
            float span = fmaxf(mx - mn, 1e-30f);
            g_tmin  = mn;
            g_dt    = span / (float)(RES - 1);
            g_scale = (float)(RES - 1) / span;
        }
    }
}

// ---------------------------------------------------------------------------
// K2: scatter pairs into grid-aligned midpoint buckets.
// ---------------------------------------------------------------------------
__global__ void __launch_bounds__(256) scatter_kernel(const float2* __restrict__ pairs) {
    const float tmin = g_tmin, scale = g_scale;
    const int i = blockIdx.x * 256 + threadIdx.x;
    float2 p = pairs[i];
    float m = 0.5f * (p.x + p.y);
    int b = (int)((m - tmin) * scale);
    b = min(NB - 1, max(0, b));
    int pos = atomicAdd(&g_count[b], 1);
    if (pos < CAP) g_slab[b * CAP + pos] = p;
}

// ---------------------------------------------------------------------------
// K3: warp per 32-bucket group.
//   lane = bucket within group: build level-0 list, then
//   shfl_up  Hillis-Steele -> exclusive prefix (deaths, desc)
//   shfl_down Hillis-Steele -> inclusive suffix (births, asc)
// ---------------------------------------------------------------------------
__global__ void __launch_bounds__(256) group_kernel() {
    const int warp  = (blockIdx.x * 256 + threadIdx.x) >> 5;  // group 0..127
    const int lane  = threadIdx.x & 31;
    const int bkt   = warp * 32 + lane;

    // level-0 list for this bucket
    float d0=NEGINF,d1=NEGINF,d2=NEGINF,d3=NEGINF,d4=NEGINF;
    float b0=POSINF,b1=POSINF,b2=POSINF,b3=POSINF,b4=POSINF;
    const int n = min(g_count[bkt], CAP);
    const float2* s = &g_slab[bkt * CAP];
    for (int k = 0; k < n; k++) {
        float2 p = s[k];
        insert_desc(d0, d1, d2, d3, d4, p.y);
        insert_asc (b0, b1, b2, b3, b4, p.x);
    }

    // inclusive prefix scan of deaths (desc)
    float i0=d0, i1=d1, i2=d2, i3=d3, i4=d4;
    #pragma unroll
    for (int off = 1; off < 32; off <<= 1) {
        float e0 = __shfl_up_sync(0xffffffffu, i0, off);
        float e1 = __shfl_up_sync(0xffffffffu, i1, off);
        float e2 = __shfl_up_sync(0xffffffffu, i2, off);
        float e3 = __shfl_up_sync(0xffffffffu, i3, off);
        float e4 = __shfl_up_sync(0xffffffffu, i4, off);
        if (lane >= off) merge_desc(i0,i1,i2,i3,i4, e0,e1,e2,e3,e4);
    }
    // exclusive prefix = shift inclusive up by one lane
    float p0 = __shfl_up_sync(0xffffffffu, i0, 1);
    float p1 = __shfl_up_sync(0xffffffffu, i1, 1);
    float p2 = __shfl_up_sync(0xffffffffu, i2, 1);
    float p3 = __shfl_up_sync(0xffffffffu, i3, 1);
    float p4 = __shfl_up_sync(0xffffffffu, i4, 1);
    if (lane == 0) { p0=NEGINF; p1=NEGINF; p2=NEGINF; p3=NEGINF; p4=NEGINF; }
    g_Pf[bkt][0]=p0; g_Pf[bkt][1]=p1; g_Pf[bkt][2]=p2; g_Pf[bkt][3]=p3; g_Pf[bkt][4]=p4;
    if (lane == 31) {
        g_GT[warp][0]=i0; g_GT[warp][1]=i1; g_GT[warp][2]=i2;
        g_GT[warp][3]=i3; g_GT[warp][4]=i4;
    }

    // inclusive suffix scan of births (asc)
    float u0=b0, u1=b1, u2=b2, u3=b3, u4=b4;
    #pragma unroll
    for (int off = 1; off < 32; off <<= 1) {
        float e0 = __shfl_down_sync(0xffffffffu, u0, off);
        float e1 = __shfl_down_sync(0xffffffffu, u1, off);
        float e2 = __shfl_down_sync(0xffffffffu, u2, off);
        float e3 = __shfl_down_sync(0xffffffffu, u3, off);
        float e4 = __shfl_down_sync(0xffffffffu, u4, off);
        if (lane + off < 32) merge_asc(u0,u1,u2,u3,u4, e0,e1,e2,e3,e4);
    }
    g_Sf[bkt][0]=u0; g_Sf[bkt][1]=u1; g_Sf[bkt][2]=u2; g_Sf[bkt][3]=u3; g_Sf[bkt][4]=u4;
    if (lane == 0) {
        g_GB[warp][0]=u0; g_GB[warp][1]=u1; g_GB[warp][2]=u2;
        g_GB[warp][3]=u3; g_GB[warp][4]=u4;
    }
}

// ---------------------------------------------------------------------------
// K4: block of 128 threads -> 128 columns.
//   Redundant per-block coarse scan over the 128 group totals (smem ping-pong),
//   then 2 merges per column.
// ---------------------------------------------------------------------------
__global__ void __launch_bounds__(128) landscape_kernel(float* __restrict__ out)
{
    __shared__ float sP[2][NGROUP][5], sS[2][NGROUP][5];
    const int tid = threadIdx.x;

    // load group totals, shifted for exclusivity
    if (tid > 0) {
        sP[0][tid][0]=g_GT[tid-1][0]; sP[0][tid][1]=g_GT[tid-1][1];
        sP[0][tid][2]=g_GT[tid-1][2]; sP[0][tid][3]=g_GT[tid-1][3];
        sP[0][tid][4]=g_GT[tid-1][4];
    } else {
        sP[0][0][0]=NEGINF; sP[0][0][1]=NEGINF; sP[0][0][2]=NEGINF;
        sP[0][0][3]=NEGINF; sP[0][0][4]=NEGINF;
    }
    if (tid < NGROUP - 1) {
        sS[0][tid][0]=g_GB[tid+1][0]; sS[0][tid][1]=g_GB[tid+1][1];
        sS[0][tid][2]=g_GB[tid+1][2]; sS[0][tid][3]=g_GB[tid+1][3];
        sS[0][tid][4]=g_GB[tid+1][4];
    } else {
        sS[0][tid][0]=POSINF; sS[0][tid][1]=POSINF; sS[0][tid][2]=POSINF;
        sS[0][tid][3]=POSINF; sS[0][tid][4]=POSINF;
    }
    __syncthreads();

    int cur = 0;
    #pragma unroll
    for (int off = 1; off < NGROUP; off <<= 1) {
        float a0=sP[cur][tid][0], a1=sP[cur][tid][1], a2=sP[cur][tid][2],
              a3=sP[cur][tid][3], a4=sP[cur][tid][4];
        if (tid >= off)
            merge_desc(a0,a1,a2,a3,a4,
                       sP[cur][tid-off][0], sP[cur][tid-off][1],
                       sP[cur][tid-off][2], sP[cur][tid-off][3],
                       sP[cur][tid-off][4]);
        sP[cur^1][tid][0]=a0; sP[cur^1][tid][1]=a1; sP[cur^1][tid][2]=a2;
        sP[cur^1][tid][3]=a3; sP[cur^1][tid][4]=a4;

        float u0=sS[cur][tid][0], u1=sS[cur][tid][1], u2=sS[cur][tid][2],
              u3=sS[cur][tid][3], u4=sS[cur][tid][4];
        if (tid + off < NGROUP)
            merge_asc(u0,u1,u2,u3,u4,
                      sS[cur][tid+off][0], sS[cur][tid+off][1],
                      sS[cur][tid+off][2], sS[cur][tid+off][3],
                      sS[cur][tid+off][4]);
        sS[cur^1][tid][0]=u0; sS[cur^1][tid][1]=u1; sS[cur^1][tid][2]=u2;
        sS[cur^1][tid][3]=u3; sS[cur^1][tid][4]=u4;
        cur ^= 1;
        __syncthreads();
    }

    // per-column assembly
    const int j = blockIdx.x * 128 + tid;          // column 0..4095
    const float t = g_tmin + (float)j * g_dt;
    const int g = j >> 5;

    float p0=g_Pf[j][0], p1=g_Pf[j][1], p2=g_Pf[j][2], p3=g_Pf[j][3], p4=g_Pf[j][4];
    merge_desc(p0,p1,p2,p3,p4,
               sP[cur][g][0], sP[cur][g][1], sP[cur][g][2],
               sP[cur][g][3], sP[cur][g][4]);

    float s0=g_Sf[j][0], s1=g_Sf[j][1], s2=g_Sf[j][2], s3=g_Sf[j][3], s4=g_Sf[j][4];
    merge_asc(s0,s1,s2,s3,s4,
              sS[cur][g][0], sS[cur][g][1], sS[cur][g][2],
              sS[cur][g][3], sS[cur][g][4]);

    // transform to tent values (clamp keeps order), final merge, write.
    p0 = fmaxf(p0 - t, 0.0f); p1 = fmaxf(p1 - t, 0.0f); p2 = fmaxf(p2 - t, 0.0f);
    p3 = fmaxf(p3 - t, 0.0f); p4 = fmaxf(p4 - t, 0.0f);
    float q0 = fmaxf(t - s0, 0.0f), q1 = fmaxf(t - s1, 0.0f);
    float q2 = fmaxf(t - s2, 0.0f), q3 = fmaxf(t - s3, 0.0f);
    float q4 = fmaxf(t - s4, 0.0f);
    merge_desc(p0,p1,p2,p3,p4, q0,q1,q2,q3,q4);

    out[0 * RES + j] = p0;
    out[1 * RES + j] = p1;
    out[2 * RES + j] = p2;
    out[3 * RES + j] = p3;
    out[4 * RES + j] = p4;
}

extern "C" void kernel_launch(void* const* d_in, const int* in_sizes, int n_in,
                              void* d_out, int out_size) {
    const float2* pairs = (const float2*)d_in[0];
    float* out = (float*)d_out;

    minmax_kernel   <<<1, 1024>>>(pairs);
    scatter_kernel  <<<N_PAIRS / 256, 256>>>(pairs);
    group_kernel    <<<NB / 32 / 8, 256>>>();   // 128 warps = 16 blocks x 8 warps
    landscape_kernel<<<RES / 128, 128>>>(out);
}

// round 7
// speedup vs baseline: 1.9225x; 1.0206x over previous
#include <cuda_runtime.h>

// PersistenceLandscapeEncoder: pairs (32768,2) f32 -> landscapes (5,4096) f32.
//
// tent_i(t) = min(t-b_i, d_i-t) clamped at 0.  With m=(b+d)/2:
//   m <  t  ->  value = d - t ;  m >= t -> value = t - b
// Buckets aligned to the t-grid (4096).  Column j:
//   top5 = merge( {prefixTop5d(buckets<j) - t}+ , {t - suffixBot5b(buckets>=j)}+ )
//
// K1 wide atomic minmax   K2 scatter(+derive tmin/dt)   K3 warp group scans
// K4 columns: 2-barrier warp-hierarchical coarse scan + gather/merge.
// Replay-safe state: g_amin/g_amax reset by K4 tail; g_count reset by K3.

#define N_PAIRS 32768
#define RES     4096
#define NB      4096
#define CAP     64
#define NGROUP  128          // NB / 32
#define NEGINF  (-3.0e38f)
#define POSINF  (3.0e38f)

__device__ unsigned g_amin = 0xFFFFFFFFu;   // ordered-uint encodings
__device__ unsigned g_amax = 0u;
__device__ float  g_tmin, g_dt, g_scale;
__device__ int    g_count[NB];              // static zero-init; K3 re-zeroes
__device__ float2 g_slab[NB * CAP];
__device__ float4 g_Pf4[NB];  __device__ float g_Pf1[NB];  // excl prefix top5 d
__device__ float4 g_Sf4[NB];  __device__ float g_Sf1[NB];  // incl suffix bot5 b
__device__ float  g_GT[NGROUP][5];   // group total top-5 d (desc)
__device__ float  g_GB[NGROUP][5];   // group total bot-5 b (asc)

__device__ __forceinline__ unsigned enc(float f) {
    int i = __float_as_int(f);
    return (unsigned)(i ^ ((i >> 31) | 0x80000000));
}
__device__ __forceinline__ float dec(unsigned u) {
    int i = (u & 0x80000000u) ? (int)(u ^ 0x80000000u) : ~(int)u;
    return __int_as_float(i);
}

// ---- sorted 5-list networks (static indices only) --------------------------
__device__ __forceinline__ void merge_desc(
    float& a0, float& a1, float& a2, float& a3, float& a4,
    float b0, float b1, float b2, float b3, float b4)
{
    float m0 = fmaxf(a0, b0);
    float m1 = fmaxf(fmaxf(a1, b1), fminf(a0, b0));
    float m2 = fmaxf(fmaxf(a2, b2), fmaxf(fminf(a0, b1), fminf(a1, b0)));
    float m3 = fmaxf(fmaxf(a3, b3),
               fmaxf(fminf(a0, b2), fmaxf(fminf(a1, b1), fminf(a2, b0))));
    float m4 = fmaxf(fmaxf(a4, b4),
               fmaxf(fmaxf(fminf(a0, b3), fminf(a1, b2)),
                     fmaxf(fminf(a2, b1), fminf(a3, b0))));
    a0 = m0; a1 = m1; a2 = m2; a3 = m3; a4 = m4;
}

__device__ __forceinline__ void merge_asc(
    float& a0, float& a1, float& a2, float& a3, float& a4,
    float b0, float b1, float b2, float b3, float b4)
{
    float m0 = fminf(a0, b0);
    float m1 = fminf(fminf(a1, b1), fmaxf(a0, b0));
    float m2 = fminf(fminf(a2, b2), fminf(fmaxf(a0, b1), fmaxf(a1, b0)));
    float m3 = fminf(fminf(a3, b3),
               fminf(fmaxf(a0, b2), fminf(fmaxf(a1, b1), fmaxf(a2, b0))));
    float m4 = fminf(fminf(a4, b4),
               fminf(fminf(fmaxf(a0, b3), fmaxf(a1, b2)),
                     fminf(fmaxf(a2, b1), fmaxf(a3, b0))));
    a0 = m0; a1 = m1; a2 = m2; a3 = m3; a4 = m4;
}

__device__ __forceinline__ void insert_desc(
    float& t0, float& t1, float& t2, float& t3, float& t4, float v)
{
    if (v > t4) {
        t4 = v;
        if (t4 > t3) { float x = t4; t4 = t3; t3 = x;
          if (t3 > t2) { x = t3; t3 = t2; t2 = x;
            if (t2 > t1) { x = t2; t2 = t1; t1 = x;
              if (t1 > t0) { x = t1; t1 = t0; t0 = x; }
            }
          }
        }
    }
}

__device__ __forceinline__ void insert_asc(
    float& t0, float& t1, float& t2, float& t3, float& t4, float v)
{
    if (v < t4) {
        t4 = v;
        if (t4 < t3) { float x = t4; t4 = t3; t3 = x;
          if (t3 < t2) { x = t3; t3 = t2; t2 = x;
            if (t2 < t1) { x = t2; t2 = t1; t1 = x;
              if (t1 < t0) { x = t1; t1 = t0; t0 = x; }
            }
          }
        }
    }
}

// ---------------------------------------------------------------------------
// K1: wide minmax -> atomic encoded min/max.  64 blocks x 256, 1 float4 each.
// ---------------------------------------------------------------------------
__global__ void __launch_bounds__(256) minmax_kernel(const float2* __restrict__ pairs) {
    __shared__ float smn[8], smx[8];
    const int tid = threadIdx.x;
    const float4 v = ((const float4*)pairs)[blockIdx.x * 256 + tid];  // (b,d,b,d)
    float mn = fminf(v.x, v.z);
    float mx = fmaxf(v.y, v.w);
    #pragma unroll
    for (int off = 16; off >= 1; off >>= 1) {
        mn = fminf(mn, __shfl_xor_sync(0xffffffffu, mn, off));
        mx = fmaxf(mx, __shfl_xor_sync(0xffffffffu, mx, off));
    }
    if ((tid & 31) == 0) { smn[tid >> 5] = mn; smx[tid >> 5] = mx; }
    __syncthreads();
    if (tid < 8) {
        mn = smn[tid]; mx = smx[tid];
        #pragma unroll
        for (int off = 4; off >= 1; off >>= 1) {
            mn = fminf(mn, __shfl_xor_sync(0xffu, mn, off));
            mx = fmaxf(mx, __shfl_xor_sync(0xffu, mx, off));
        }
        if (tid == 0) {
            atomicMin(&g_amin, enc(mn));
            atomicMax(&g_amax, enc(mx));
        }
    }
}

// ---------------------------------------------------------------------------
// K2: scatter into grid-aligned midpoint buckets; publish derived tmin/dt.
// ---------------------------------------------------------------------------
__global__ void __launch_bounds__(256) scatter_kernel(const float2* __restrict__ pairs) {
    const float tmin = dec(g_amin);
    const float tmax = dec(g_amax);
    const float span = fmaxf(tmax - tmin, 1e-30f);
    const float scale = (float)(RES - 1) / span;
    const int i = blockIdx.x * 256 + threadIdx.x;
    if (i == 0) {
        g_tmin  = tmin;
        g_dt    = span / (float)(RES - 1);
        g_scale = scale;
    }
    float2 p = pairs[i];
    float m = 0.5f * (p.x + p.y);
    int b = (int)((m - tmin) * scale);
    b = min(NB - 1, max(0, b));
    int pos = atomicAdd(&g_count[b], 1);
    if (pos < CAP) g_slab[b * CAP + pos] = p;
}

// ---------------------------------------------------------------------------
// K3: warp per 32-bucket group: level-0 lists + shfl prefix/suffix scans.
//     Re-zeroes g_count for the next graph replay.
// ---------------------------------------------------------------------------
__global__ void __launch_bounds__(256) group_kernel() {
    const int warp = (blockIdx.x * 256 + threadIdx.x) >> 5;  // group 0..127
    const int lane = threadIdx.x & 31;
    const int bkt  = warp * 32 + lane;

    float d0=NEGINF,d1=NEGINF,d2=NEGINF,d3=NEGINF,d4=NEGINF;
    float b0=POSINF,b1=POSINF,b2=POSINF,b3=POSINF,b4=POSINF;
    const int n = min(g_count[bkt], CAP);
    g_count[bkt] = 0;                       // replay-safe reset (sole toucher)
    const float2* s = &g_slab[bkt * CAP];
    for (int k = 0; k < n; k++) {
        float2 p = s[k];
        insert_desc(d0, d1, d2, d3, d4, p.y);
        insert_asc (b0, b1, b2, b3, b4, p.x);
    }

    // inclusive prefix scan of deaths (desc)
    float i0=d0, i1=d1, i2=d2, i3=d3, i4=d4;
    #pragma unroll
    for (int off = 1; off < 32; off <<= 1) {
        float e0 = __shfl_up_sync(0xffffffffu, i0, off);
        float e1 = __shfl_up_sync(0xffffffffu, i1, off);
        float e2 = __shfl_up_sync(0xffffffffu, i2, off);
        float e3 = __shfl_up_sync(0xffffffffu, i3, off);
        float e4 = __shfl_up_sync(0xffffffffu, i4, off);
        if (lane >= off) merge_desc(i0,i1,i2,i3,i4, e0,e1,e2,e3,e4);
    }
    float p0 = __shfl_up_sync(0xffffffffu, i0, 1);
    float p1 = __shfl_up_sync(0xffffffffu, i1, 1);
    float p2 = __shfl_up_sync(0xffffffffu, i2, 1);
    float p3 = __shfl_up_sync(0xffffffffu, i3, 1);
    float p4 = __shfl_up_sync(0xffffffffu, i4, 1);
    if (lane == 0) { p0=NEGINF; p1=NEGINF; p2=NEGINF; p3=NEGINF; p4=NEGINF; }
    g_Pf4[bkt] = make_float4(p0, p1, p2, p3);
    g_Pf1[bkt] = p4;
    if (lane == 31) {
        g_GT[warp][0]=i0; g_GT[warp][1]=i1; g_GT[warp][2]=i2;
        g_GT[warp][3]=i3; g_GT[warp][4]=i4;
    }

    // inclusive suffix scan of births (asc)
    float u0=b0, u1=b1, u2=b2, u3=b3, u4=b4;
    #pragma unroll
    for (int off = 1; off < 32; off <<= 1) {
        float e0 = __shfl_down_sync(0xffffffffu, u0, off);
        float e1 = __shfl_down_sync(0xffffffffu, u1, off);
        float e2 = __shfl_down_sync(0xffffffffu, u2, off);
        float e3 = __shfl_down_sync(0xffffffffu, u3, off);
        float e4 = __shfl_down_sync(0xffffffffu, u4, off);
        if (lane + off < 32) merge_asc(u0,u1,u2,u3,u4, e0,e1,e2,e3,e4);
    }
    g_Sf4[bkt] = make_float4(u0, u1, u2, u3);
    g_Sf1[bkt] = u4;
    if (lane == 0) {
        g_GB[warp][0]=u0; g_GB[warp][1]=u1; g_GB[warp][2]=u2;
        g_GB[warp][3]=u3; g_GB[warp][4]=u4;
    }
}

// ---------------------------------------------------------------------------
// K4: 8 blocks x 512 threads -> 512 columns each.
//   Warp-hierarchical redundant coarse scan (2 barriers), then per-column
//   gather + merges.  Tail resets g_amin/g_amax for next replay.
// ---------------------------------------------------------------------------
__global__ void __launch_bounds__(512) landscape_kernel(float* __restrict__ out)
{
    __shared__ float sPc[NGROUP][5], sSc[NGROUP][5];
    __shared__ float wtP[4][5], wtS[4][5];
    const int tid = threadIdx.x;

    if (tid < NGROUP) {
        // ---- prefix side: scan shifted GT (A'[g] = GT[g-1]) ----
        const int g = tid, w = tid >> 5, lane = tid & 31;
        float a0=NEGINF,a1=NEGINF,a2=NEGINF,a3=NEGINF,a4=NEGINF;
        if (g > 0) { a0=g_GT[g-1][0]; a1=g_GT[g-1][1]; a2=g_GT[g-1][2];
                     a3=g_GT[g-1][3]; a4=g_GT[g-1][4]; }
        #pragma unroll
        for (int off = 1; off < 32; off <<= 1) {
            float e0 = __shfl_up_sync(0xffffffffu, a0, off);
            float e1 = __shfl_up_sync(0xffffffffu, a1, off);
            float e2 = __shfl_up_sync(0xffffffffu, a2, off);
            float e3 = __shfl_up_sync(0xffffffffu, a3, off);
            float e4 = __shfl_up_sync(0xffffffffu, a4, off);
            if (lane >= off) merge_desc(a0,a1,a2,a3,a4, e0,e1,e2,e3,e4);
        }
        if (lane == 31) { wtP[w][0]=a0; wtP[w][1]=a1; wtP[w][2]=a2;
                          wtP[w][3]=a3; wtP[w][4]=a4; }
        sPc[g][0]=a0; sPc[g][1]=a1; sPc[g][2]=a2; sPc[g][3]=a3; sPc[g][4]=a4;
    } else if (tid < 2 * NGROUP) {
        // ---- suffix side: scan shifted GB (A''[g] = GB[g+1]) ----
        const int g = tid - NGROUP, w = g >> 5, lane = g & 31;
        float a0=POSINF,a1=POSINF,a2=POSINF,a3=POSINF,a4=POSINF;
        if (g < NGROUP - 1) { a0=g_GB[g+1][0]; a1=g_GB[g+1][1]; a2=g_GB[g+1][2];
                              a3=g_GB[g+1][3]; a4=g_GB[g+1][4]; }
        #pragma unroll
        for (int off = 1; off < 32; off <<= 1) {
            float e0 = __shfl_down_sync(0xffffffffu, a0, off);
            float e1 = __shfl_down_sync(0xffffffffu, a1, off);
            float e2 = __shfl_down_sync(0xffffffffu, a2, off);
            float e3 = __shfl_down_sync(0xffffffffu, a3, off);
            float e4 = __shfl_down_sync(0xffffffffu, a4, off);
            if (lane + off < 32) merge_asc(a0,a1,a2,a3,a4, e0,e1,e2,e3,e4);
        }
        if (lane == 0) { wtS[w][0]=a0; wtS[w][1]=a1; wtS[w][2]=a2;
                         wtS[w][3]=a3; wtS[w][4]=a4; }
        sSc[g][0]=a0; sSc[g][1]=a1; sSc[g][2]=a2; sSc[g][3]=a3; sSc[g][4]=a4;
    }
    __syncthreads();

    // cross-warp fixup: prefix merges preceding warp totals, suffix following.
    if (tid < NGROUP) {
        const int g = tid, w = tid >> 5;
        if (w > 0) {
            float a0=sPc[g][0], a1=sPc[g][1], a2=sPc[g][2],
                  a3=sPc[g][3], a4=sPc[g][4];
            #pragma unroll
            for (int q = 0; q < 3; q++)
                if (q < w)
                    merge_desc(a0,a1,a2,a3,a4,
                               wtP[q][0], wtP[q][1], wtP[q][2], wtP[q][3], wtP[q][4]);
            sPc[g][0]=a0; sPc[g][1]=a1; sPc[g][2]=a2; sPc[g][3]=a3; sPc[g][4]=a4;
        }
    } else if (tid < 2 * NGROUP) {
        const int g = tid - NGROUP, w = g >> 5;
        if (w < 3) {
            float a0=sSc[g][0], a1=sSc[g][1], a2=sSc[g][2],
                  a3=sSc[g][3], a4=sSc[g][4];
            #pragma unroll
            for (int q = 1; q < 4; q++)
                if (q > w)
                    merge_asc(a0,a1,a2,a3,a4,
                              wtS[q][0], wtS[q][1], wtS[q][2], wtS[q][3], wtS[q][4]);
            sSc[g][0]=a0; sSc[g][1]=a1; sSc[g][2]=a2; sSc[g][3]=a3; sSc[g][4]=a4;
        }
    }
    __syncthreads();

    // ---- per-column assembly ----
    const int j = blockIdx.x * 512 + tid;          // column 0..4095
    const float t = g_tmin + (float)j * g_dt;
    const int g = j >> 5;

    float4 pf = g_Pf4[j]; float pf4 = g_Pf1[j];
    float p0=pf.x, p1=pf.y, p2=pf.z, p3=pf.w, p4=pf4;
    merge_desc(p0,p1,p2,p3,p4,
               sPc[g][0], sPc[g][1], sPc[g][2], sPc[g][3], sPc[g][4]);

    float4 sf = g_Sf4[j]; float sf4 = g_Sf1[j];
    float s0=sf.x, s1=sf.y, s2=sf.z, s3=sf.w, s4=sf4;
    merge_asc(s0,s1,s2,s3,s4,
              sSc[g][0], sSc[g][1], sSc[g][2], sSc[g][3], sSc[g][4]);

    p0 = fmaxf(p0 - t, 0.0f); p1 = fmaxf(p1 - t, 0.0f); p2 = fmaxf(p2 - t, 0.0f);
    p3 = fmaxf(p3 - t, 0.0f); p4 = fmaxf(p4 - t, 0.0f);
    float q0 = fmaxf(t - s0, 0.0f), q1 = fmaxf(t - s1, 0.0f);
    float q2 = fmaxf(t - s2, 0.0f), q3 = fmaxf(t - s3, 0.0f);
    float q4 = fmaxf(t - s4, 0.0f);
    merge_desc(p0,p1,p2,p3,p4, q0,q1,q2,q3,q4);

    out[0 * RES + j] = p0;
    out[1 * RES + j] = p1;
    out[2 * RES + j] = p2;
    out[3 * RES + j] = p3;
    out[4 * RES + j] = p4;

    // replay-safe reset of the atomic minmax (no reader of g_amin/g_amax here)
    if (blockIdx.x == 0 && tid == 0) {
        g_amin = 0xFFFFFFFFu;
        g_amax = 0u;
    }
}

extern "C" void kernel_launch(void* const* d_in, const int* in_sizes, int n_in,
                              void* d_out, int out_size) {
    const float2* pairs = (const float2*)d_in[0];
    float* out = (float*)d_out;

    minmax_kernel   <<<N_PAIRS / 2 / 256, 256>>>(pairs);   // 64 blocks
    scatter_kernel  <<<N_PAIRS / 256, 256>>>(pairs);       // 128 blocks
    group_kernel    <<<NB / 32 / 8, 256>>>();              // 16 blocks
    landscape_kernel<<<RES / 512, 512>>>(out);             // 8 blocks
}